// round 5
// baseline (speedup 1.0000x reference)
#include <cuda_runtime.h>
#include <cstdint>

// YOLOv1 loss — persistent double-buffered cp.async streaming reduction.
// Accumulators: [0]=cls, [1]=obj_conf, [2]=noobj, [3]=coord
__device__ double g_acc[4];            // zero at module load; reset by last CTA each replay
__device__ unsigned int g_ticket = 0;

#define CELLS 49
#define CH 30
#define PERB 1470                  // floats per item per tensor
#define ITEMS 2                    // batch items per tile
#define NT 256
#define TILE (PERB * ITEMS)        // 2940 floats
#define TILE_BYTES (TILE * 4)      // 11760 B (16B-multiple)
#define CHUNKS (TILE / 4)          // 735 float4 per tensor
#define BUF_FLOATS (TILE * 2)      // pred + targ
#define BUF_BYTES (BUF_FLOATS * 4) // 23520 B per buffer
#define GRID_CTAS 608              // 4 per SM x 152 SMs

extern __shared__ float dyn_smem[];    // 2 * BUF_BYTES

__device__ __forceinline__ void cpa16(uint32_t s, const float* g) {
    asm volatile("cp.async.cg.shared.global [%0], [%1], 16;" :: "r"(s), "l"(g));
}

__device__ __forceinline__ void issue_tile(uint32_t sbuf,
                                           const float* __restrict__ pred,
                                           const float* __restrict__ targ,
                                           int tile, int tid) {
    const float* p = pred + (size_t)tile * TILE;
    const float* q = targ + (size_t)tile * TILE;
    const uint32_t sp_ = sbuf;
    const uint32_t st_ = sbuf + TILE_BYTES;
    for (int i = tid; i < CHUNKS; i += NT) {
        cpa16(sp_ + i * 16, p + i * 4);
        cpa16(st_ + i * 16, q + i * 4);
    }
}

__global__ __launch_bounds__(NT) void yolo_loss_pers(
    const float* __restrict__ pred, const float* __restrict__ targ,
    float* __restrict__ out, int ntiles) {
    __shared__ float bpx[ITEMS][98][4];   // pred obj boxes xyxy (compacted)
    __shared__ float btx[ITEMS][98][4];   // target obj boxes xyxy
    __shared__ short boxoff[ITEMS][98];   // float offset within tile of each box
    __shared__ int   cnt[ITEMS];
    __shared__ float red[NT / 32][4];
    __shared__ int   is_last;

    const int tid  = threadIdx.x;
    const int sub  = tid >> 7;            // item within tile
    const int stid = tid & 127;
    const int G    = gridDim.x;
    const int t0   = blockIdx.x;

    const uint32_t sbase = (uint32_t)__cvta_generic_to_shared(dyn_smem);

    if (tid < ITEMS) cnt[tid] = 0;
    if (tid == 0) is_last = 0;

    // ---- prologue: prefetch up to 2 tiles
    if (t0 < ntiles) issue_tile(sbase, pred, targ, t0, tid);
    asm volatile("cp.async.commit_group;");
    if (t0 + G < ntiles) issue_tile(sbase + BUF_BYTES, pred, targ, t0 + G, tid);
    asm volatile("cp.async.commit_group;");

    float v0 = 0.f, v1 = 0.f, v2 = 0.f, v3 = 0.f;  // cls, objc, noobj, coord

    int buf = 0;
    for (int t = t0; t < ntiles; t += G, buf ^= 1) {
        asm volatile("cp.async.wait_group 1;");
        __syncthreads();                               // (A) data visible; cnt reset visible
        const float* sp = dyn_smem + buf * BUF_FLOATS;
        const float* st = sp + TILE;

        // ---- B1: per-cell noobj + obj-box compaction (threads 0..97, one per cell)
        if (tid < ITEMS * CELLS) {
            const int base = tid * CH;
            const float conf = st[base + 4];          // exactly 0 or 1
            if (conf == 0.0f) {
                const float d4 = sp[base + 4] - st[base + 4];
                const float d9 = sp[base + 9] - st[base + 9];
                v2 += d4 * d4 + d9 * d9;
            } else {
                const int s_ = tid / CELLS;
                const int slot = atomicAdd(&cnt[s_], 1);
                #pragma unroll
                for (int k = 0; k < 2; k++) {
                    const int j   = slot * 2 + k;
                    const int off = base + k * 5;
                    boxoff[s_][j] = (short)off;
                    const float pcx = sp[off],     pcy = sp[off + 1];
                    const float pw  = sp[off + 2], ph  = sp[off + 3];
                    bpx[s_][j][0] = pcx - pw * 0.5f;  bpx[s_][j][1] = pcy - ph * 0.5f;
                    bpx[s_][j][2] = pcx + pw * 0.5f;  bpx[s_][j][3] = pcy + ph * 0.5f;
                    const float tcx = st[off],     tcy = st[off + 1];
                    const float tw  = st[off + 2], th  = st[off + 3];
                    btx[s_][j][0] = tcx - tw * 0.5f;  btx[s_][j][1] = tcy - th * 0.5f;
                    btx[s_][j][2] = tcx + tw * 0.5f;  btx[s_][j][3] = tcy + th * 0.5f;
                }
            }
        }

        // ---- B2: class loss, flat over all 256 threads (obj mask as multiplier)
        for (int e = tid; e < ITEMS * CELLS * 20; e += NT) {
            const int cg   = e / 20;                  // global cell 0..97
            const int base = cg * CH;
            const int c    = base + 10 + (e - cg * 20);
            const float m  = st[base + 4];            // 0 or 1
            const float d  = sp[c] - st[c];
            v0 += m * (d * d);
        }
        __syncthreads();                               // (B) boxes + cnt visible

        // ---- C: cmask[j] = any obj pred box overlaps target box j.
        // iou > 0 <=> inter > 0 (union always > 0 since w,h >= 0.05).
        const int nb = cnt[sub] * 2;
        if (stid < nb) {
            const float tx0 = btx[sub][stid][0], ty0 = btx[sub][stid][1];
            const float tx1 = btx[sub][stid][2], ty1 = btx[sub][stid][3];
            bool hit = false;
            for (int i = 0; i < nb; i++) {
                const float w = fminf(bpx[sub][i][2], tx1) - fmaxf(bpx[sub][i][0], tx0);
                const float h = fminf(bpx[sub][i][3], ty1) - fmaxf(bpx[sub][i][1], ty0);
                if (w > 0.0f && h > 0.0f) { hit = true; break; }
            }
            if (hit) {
                const int off = boxoff[sub][stid];
                const float dx = sp[off]     - st[off];
                const float dy = sp[off + 1] - st[off + 1];
                const float dw = sqrtf(sp[off + 2]) - sqrtf(st[off + 2]);
                const float dh = sqrtf(sp[off + 3]) - sqrtf(st[off + 3]);
                v3 += dx * dx + dy * dy + dw * dw + dh * dh;
                const float dc = sp[off + 4] - st[off + 4];
                v1 += dc * dc;
            }
        }
        __syncthreads();                               // (C) buffer + cnt free
        if (tid < ITEMS) cnt[tid] = 0;

        const int nt2 = t + 2 * G;
        if (nt2 < ntiles) issue_tile(sbase + buf * BUF_BYTES, pred, targ, nt2, tid);
        asm volatile("cp.async.commit_group;");
    }

    // ---- block reduction of per-thread accumulators
    #pragma unroll
    for (int o = 16; o > 0; o >>= 1) {
        v0 += __shfl_down_sync(0xffffffffu, v0, o);
        v1 += __shfl_down_sync(0xffffffffu, v1, o);
        v2 += __shfl_down_sync(0xffffffffu, v2, o);
        v3 += __shfl_down_sync(0xffffffffu, v3, o);
    }
    const int lane = tid & 31, warp = tid >> 5;
    if (lane == 0) {
        red[warp][0] = v0; red[warp][1] = v1;
        red[warp][2] = v2; red[warp][3] = v3;
    }
    __syncthreads();
    if (tid < 4) {
        float s = 0.0f;
        #pragma unroll
        for (int w = 0; w < NT / 32; w++) s += red[w][tid];
        atomicAdd(&g_acc[tid], (double)s);
        __threadfence();
    }
    __syncthreads();

    // ---- ticket; last CTA finalizes + resets for next graph replay
    if (tid == 0) {
        const unsigned int old = atomicAdd(&g_ticket, 1u);
        if (old == gridDim.x - 1) is_last = 1;
    }
    __syncthreads();
    if (is_last && tid == 0) {
        const double cls_s   = atomicAdd(&g_acc[0], 0.0);
        const double objc_s  = atomicAdd(&g_acc[1], 0.0);
        const double noobj_s = atomicAdd(&g_acc[2], 0.0);
        const double coord_s = atomicAdd(&g_acc[3], 0.0);
        const double invB = 1.0 / (double)(ntiles * ITEMS);
        const float bcls   = (float)(cls_s * invB);
        const float bobj   = (float)((objc_s + 0.5 * noobj_s) * invB);
        const float bcoord = (float)(coord_s * 5.0 * invB);
        out[0] = bcls + bobj + bcoord;
        out[1] = bcls;
        out[2] = bobj;
        out[3] = bcoord;
        g_acc[0] = 0.0; g_acc[1] = 0.0; g_acc[2] = 0.0; g_acc[3] = 0.0;
        __threadfence();
        g_ticket = 0u;
    }
}

extern "C" void kernel_launch(void* const* d_in, const int* in_sizes, int n_in,
                              void* d_out, int out_size) {
    const float* pred = (const float*)d_in[0];
    const float* targ = (const float*)d_in[1];
    float* out = (float*)d_out;
    const int B = in_sizes[0] / PERB;        // 8192
    const int ntiles = B / ITEMS;            // 4096

    static bool attr_set = false;            // idempotent host-side config, not a work guard
    if (!attr_set) {
        cudaFuncSetAttribute(yolo_loss_pers,
                             cudaFuncAttributeMaxDynamicSharedMemorySize,
                             2 * BUF_BYTES);
        attr_set = true;
    }
    const int grid = (ntiles < GRID_CTAS) ? ntiles : GRID_CTAS;
    yolo_loss_pers<<<grid, NT, 2 * BUF_BYTES>>>(pred, targ, out, ntiles);
}

// round 7
// speedup vs baseline: 1.0609x; 1.0609x over previous
#include <cuda_runtime.h>
#include <cstdint>

// YOLOv1 loss — persistent, double-buffered cp.async pipeline with
// intra-CTA warp specialization (warps 0-3: masks/boxes/overlap; warps 4-7: class loss).
// Accumulators: [0]=cls, [1]=obj_conf, [2]=noobj, [3]=coord
__device__ double g_acc[4];            // zero at module load; reset by last CTA each replay
__device__ unsigned int g_ticket = 0;

#define CELLS 49
#define CH 30
#define PERB 1470                  // floats per item per tensor
#define ITEMS 2                    // batch items per tile
#define NT 256
#define TILE (PERB * ITEMS)        // 2940 floats
#define TILE_BYTES (TILE * 4)      // 11760 B
#define CHUNKS (TILE / 4)          // 735 float4 per tensor
#define BUF_FLOATS (TILE * 2)      // pred + targ
#define BUF_BYTES (BUF_FLOATS * 4) // 23520 B per buffer
#define GRID_CTAS 608              // 4 per SM x 152 SMs

extern __shared__ float dyn_smem[];    // 2 * BUF_BYTES

__device__ __forceinline__ void cpa16(uint32_t s, const float* g) {
    asm volatile("cp.async.cg.shared.global [%0], [%1], 16;" :: "r"(s), "l"(g));
}

__device__ __forceinline__ void issue_tile(uint32_t sbuf,
                                           const float* __restrict__ pred,
                                           const float* __restrict__ targ,
                                           int tile, int tid) {
    const float* p = pred + (size_t)tile * TILE;
    const float* q = targ + (size_t)tile * TILE;
    #pragma unroll
    for (int i = tid; i < CHUNKS; i += NT) {
        cpa16(sbuf + i * 16, p + i * 4);
        cpa16(sbuf + TILE_BYTES + i * 16, q + i * 4);
    }
}

__global__ __launch_bounds__(NT) void yolo_loss_ws(
    const float* __restrict__ pred, const float* __restrict__ targ,
    float* __restrict__ out, int ntiles) {
    __shared__ float bpx[ITEMS][98][4];   // pred obj boxes xyxy (compacted)
    __shared__ float btx[ITEMS][98][4];   // target obj boxes xyxy
    __shared__ short boxoff[ITEMS][98];   // float offset within tile of each box
    __shared__ int   cnt[ITEMS];
    __shared__ float red[NT / 32][4];
    __shared__ int   is_last;

    const int tid  = threadIdx.x;
    const int G    = gridDim.x;
    const int t0   = blockIdx.x;
    const bool grpA = tid < 128;          // warps 0-3: B1 + C
    // warps 4-7: class loss, one thread per cell (threads 128..225)
    const int ctid = tid - 128;           // cell index for class group

    const uint32_t sbase = (uint32_t)__cvta_generic_to_shared(dyn_smem);

    if (tid < ITEMS) cnt[tid] = 0;
    if (tid == 0) is_last = 0;

    // ---- prologue: prefetch 2 tiles
    if (t0 < ntiles) issue_tile(sbase, pred, targ, t0, tid);
    asm volatile("cp.async.commit_group;");
    if (t0 + G < ntiles) issue_tile(sbase + BUF_BYTES, pred, targ, t0 + G, tid);
    asm volatile("cp.async.commit_group;");

    float v0 = 0.f, v1 = 0.f, v2 = 0.f, v3 = 0.f;  // cls, objc, noobj, coord

    int buf = 0;
    for (int t = t0; t < ntiles; t += G, buf ^= 1) {
        asm volatile("cp.async.wait_group 1;");
        __syncthreads();                               // (A) tile data + cnt reset visible
        const float* sp = dyn_smem + buf * BUF_FLOATS;
        const float* st = sp + TILE;

        if (grpA) {
            // ---- B1: per-cell noobj + obj-box compaction (threads 0..97)
            if (tid < ITEMS * CELLS) {
                const int base = tid * CH;
                if (st[base + 4] == 0.0f) {            // noobj cell
                    const float d4 = sp[base + 4] - st[base + 4];
                    const float d9 = sp[base + 9] - st[base + 9];
                    v2 += d4 * d4 + d9 * d9;
                } else {                               // obj cell: emit 2 boxes
                    const int s_ = (tid >= CELLS);
                    const int slot = atomicAdd(&cnt[s_], 1);
                    #pragma unroll
                    for (int k = 0; k < 2; k++) {
                        const int j   = slot * 2 + k;
                        const int off = base + k * 5;
                        boxoff[s_][j] = (short)off;
                        const float pcx = sp[off],     pcy = sp[off + 1];
                        const float pw  = sp[off + 2], ph  = sp[off + 3];
                        bpx[s_][j][0] = pcx - pw * 0.5f;  bpx[s_][j][1] = pcy - ph * 0.5f;
                        bpx[s_][j][2] = pcx + pw * 0.5f;  bpx[s_][j][3] = pcy + ph * 0.5f;
                        const float tcx = st[off],     tcy = st[off + 1];
                        const float tw  = st[off + 2], th  = st[off + 3];
                        btx[s_][j][0] = tcx - tw * 0.5f;  btx[s_][j][1] = tcy - th * 0.5f;
                        btx[s_][j][2] = tcx + tw * 0.5f;  btx[s_][j][3] = tcy + th * 0.5f;
                    }
                }
            }
            asm volatile("bar.sync 1, 128;" ::: "memory");   // boxes + cnt ready (group A only)

            // ---- C: cmask[j] = any obj pred box overlaps target box j.
            // iou > 0 <=> inter > 0 (union > 0 since w,h >= 0.05).
            const int sub = tid >> 6;                  // 64 threads per item
            const int nb  = cnt[sub] * 2;
            for (int j = (tid & 63); j < nb; j += 64) {
                const float tx0 = btx[sub][j][0], ty0 = btx[sub][j][1];
                const float tx1 = btx[sub][j][2], ty1 = btx[sub][j][3];
                bool hit = false;
                for (int i = 0; i < nb; i++) {
                    const float w = fminf(bpx[sub][i][2], tx1) - fmaxf(bpx[sub][i][0], tx0);
                    const float h = fminf(bpx[sub][i][3], ty1) - fmaxf(bpx[sub][i][1], ty0);
                    if (w > 0.0f && h > 0.0f) { hit = true; break; }
                }
                if (hit) {
                    const int off = boxoff[sub][j];
                    const float dx = sp[off]     - st[off];
                    const float dy = sp[off + 1] - st[off + 1];
                    const float dw = sqrtf(sp[off + 2]) - sqrtf(st[off + 2]);
                    const float dh = sqrtf(sp[off + 3]) - sqrtf(st[off + 3]);
                    v3 += dx * dx + dy * dy + dw * dw + dh * dh;
                    const float dc = sp[off + 4] - st[off + 4];
                    v1 += dc * dc;
                }
            }
        } else {
            // ---- B2: class loss, one thread per cell, unrolled over 20 classes
            if (ctid < ITEMS * CELLS) {
                const int base = ctid * CH;
                const float m = st[base + 4];          // 0 or 1
                float s = 0.0f;
                #pragma unroll
                for (int c = 10; c < 30; c++) {
                    const float d = sp[base + c] - st[base + c];
                    s += d * d;
                }
                v0 += m * s;
            }
        }
        __syncthreads();                               // (C) buffer free for overwrite
        if (tid < ITEMS) cnt[tid] = 0;

        const int nt2 = t + 2 * G;
        if (nt2 < ntiles) issue_tile(sbase + buf * (uint32_t)BUF_BYTES, pred, targ, nt2, tid);
        asm volatile("cp.async.commit_group;");
    }

    // ---- block reduction of per-thread accumulators
    #pragma unroll
    for (int o = 16; o > 0; o >>= 1) {
        v0 += __shfl_down_sync(0xffffffffu, v0, o);
        v1 += __shfl_down_sync(0xffffffffu, v1, o);
        v2 += __shfl_down_sync(0xffffffffu, v2, o);
        v3 += __shfl_down_sync(0xffffffffu, v3, o);
    }
    const int lane = tid & 31, warp = tid >> 5;
    if (lane == 0) {
        red[warp][0] = v0; red[warp][1] = v1;
        red[warp][2] = v2; red[warp][3] = v3;
    }
    __syncthreads();
    if (tid < 4) {
        float s = 0.0f;
        #pragma unroll
        for (int w = 0; w < NT / 32; w++) s += red[w][tid];
        atomicAdd(&g_acc[tid], (double)s);
        __threadfence();
    }
    __syncthreads();

    // ---- ticket; last CTA finalizes + resets for next graph replay
    if (tid == 0) {
        const unsigned int old = atomicAdd(&g_ticket, 1u);
        if (old == gridDim.x - 1) is_last = 1;
    }
    __syncthreads();
    if (is_last && tid == 0) {
        const double cls_s   = atomicAdd(&g_acc[0], 0.0);
        const double objc_s  = atomicAdd(&g_acc[1], 0.0);
        const double noobj_s = atomicAdd(&g_acc[2], 0.0);
        const double coord_s = atomicAdd(&g_acc[3], 0.0);
        const double invB = 1.0 / (double)(ntiles * ITEMS);
        const float bcls   = (float)(cls_s * invB);
        const float bobj   = (float)((objc_s + 0.5 * noobj_s) * invB);
        const float bcoord = (float)(coord_s * 5.0 * invB);
        out[0] = bcls + bobj + bcoord;
        out[1] = bcls;
        out[2] = bobj;
        out[3] = bcoord;
        g_acc[0] = 0.0; g_acc[1] = 0.0; g_acc[2] = 0.0; g_acc[3] = 0.0;
        __threadfence();
        g_ticket = 0u;
    }
}

extern "C" void kernel_launch(void* const* d_in, const int* in_sizes, int n_in,
                              void* d_out, int out_size) {
    const float* pred = (const float*)d_in[0];
    const float* targ = (const float*)d_in[1];
    float* out = (float*)d_out;
    const int B = in_sizes[0] / PERB;        // 8192
    const int ntiles = B / ITEMS;            // 4096

    static bool attr_set = false;            // idempotent host-side config
    if (!attr_set) {
        cudaFuncSetAttribute(yolo_loss_ws,
                             cudaFuncAttributeMaxDynamicSharedMemorySize,
                             2 * BUF_BYTES);
        attr_set = true;
    }
    const int grid = (ntiles < GRID_CTAS) ? ntiles : GRID_CTAS;
    yolo_loss_ws<<<grid, NT, 2 * BUF_BYTES>>>(pred, targ, out, ntiles);
}

// round 10
// speedup vs baseline: 1.2465x; 1.1750x over previous
#include <cuda_runtime.h>
#include <cstdint>

// YOLOv1 loss — persistent TMA-bulk double-buffered pipeline, warp-specialized.
// Accumulators: [0]=cls, [1]=obj_conf, [2]=noobj, [3]=coord
__device__ double g_acc[4];            // zero at module load; reset by last CTA each replay
__device__ unsigned int g_ticket = 0;

#define CELLS 49
#define CH 30
#define PERB 1470                  // floats per item per tensor
#define ITEMS 2                    // batch items per tile
#define NT 256
#define TILE (PERB * ITEMS)        // 2940 floats
#define TILE_BYTES (TILE * 4)      // 11760 B (multiple of 16)
#define BUF_FLOATS (TILE * 2)      // pred + targ
#define BUF_BYTES (BUF_FLOATS * 4) // 23520 B per stage
#define STAGES 2
#define GRID_CTAS 608              // 4 per SM x 152 SMs

extern __shared__ float dyn_smem[];    // STAGES * BUF_BYTES, 16B-aligned

__device__ __forceinline__ void mbar_init(uint32_t mbar, uint32_t cnt_) {
    asm volatile("mbarrier.init.shared.b64 [%0], %1;" :: "r"(mbar), "r"(cnt_) : "memory");
}
__device__ __forceinline__ void mbar_expect_tx(uint32_t mbar, uint32_t bytes) {
    asm volatile("mbarrier.arrive.expect_tx.shared.b64 _, [%0], %1;"
                 :: "r"(mbar), "r"(bytes) : "memory");
}
__device__ __forceinline__ void mbar_wait(uint32_t mbar, uint32_t parity) {
    uint32_t done;
    asm volatile(
        "{\n\t.reg .pred p;\n\t"
        "mbarrier.try_wait.parity.acquire.cta.shared::cta.b64 p, [%1], %2;\n\t"
        "selp.b32 %0, 1, 0, p;\n\t}"
        : "=r"(done) : "r"(mbar), "r"(parity) : "memory");
    if (!done) {
        asm volatile(
            "{\n\t.reg .pred P1;\n\t"
            "W_%=:\n\t"
            "mbarrier.try_wait.parity.acquire.cta.shared::cta.b64 P1, [%0], %1, 0x989680;\n\t"
            "@P1 bra.uni D_%=;\n\t"
            "bra.uni W_%=;\n\t"
            "D_%=:\n\t}"
            :: "r"(mbar), "r"(parity) : "memory");
    }
}
// Canonical Hopper-era bulk copy (works for a 1-CTA cluster on sm_103a).
__device__ __forceinline__ void bulk_ld(uint32_t dst, const void* src,
                                        uint32_t bytes, uint32_t mbar) {
    asm volatile(
        "cp.async.bulk.shared::cluster.global.mbarrier::complete_tx::bytes [%0], [%1], %2, [%3];"
        :: "r"(dst), "l"(src), "r"(bytes), "r"(mbar) : "memory");
}

__global__ __launch_bounds__(NT) void yolo_loss_tma(
    const float* __restrict__ pred, const float* __restrict__ targ,
    float* __restrict__ out, int ntiles) {
    __shared__ float bpx[ITEMS][98][4];       // pred obj boxes xyxy (compacted)
    __shared__ float btx[ITEMS][98][4];       // target obj boxes xyxy
    __shared__ short boxoff[ITEMS][98];       // float offset within tile of each box
    __shared__ int   cnt[ITEMS];
    __shared__ float red[NT / 32][4];
    __shared__ int   is_last;
    __shared__ alignas(8) unsigned long long mbar_s[STAGES];

    const int tid  = threadIdx.x;
    const int G    = gridDim.x;
    const int t0   = blockIdx.x;
    const bool grpA = tid < 128;              // warps 0-3: masks/boxes/overlap
    const int ctid = tid - 128;               // warps 4-7: class loss cell idx

    const uint32_t sbase = (uint32_t)__cvta_generic_to_shared(dyn_smem);
    const uint32_t mb0   = (uint32_t)__cvta_generic_to_shared(&mbar_s[0]);

    if (tid < ITEMS) cnt[tid] = 0;
    if (tid == 0) {
        is_last = 0;
        mbar_init(mb0, 1);
        mbar_init(mb0 + 8, 1);
    }
    __syncthreads();

    // ---- prologue: one TMA bulk pair per stage, issued by thread 0 only
    if (tid == 0) {
        if (t0 < ntiles) {
            mbar_expect_tx(mb0, BUF_BYTES);
            bulk_ld(sbase, pred + (size_t)t0 * TILE, TILE_BYTES, mb0);
            bulk_ld(sbase + TILE_BYTES, targ + (size_t)t0 * TILE, TILE_BYTES, mb0);
        }
        if (t0 + G < ntiles) {
            mbar_expect_tx(mb0 + 8, BUF_BYTES);
            bulk_ld(sbase + BUF_BYTES, pred + (size_t)(t0 + G) * TILE, TILE_BYTES, mb0 + 8);
            bulk_ld(sbase + BUF_BYTES + TILE_BYTES, targ + (size_t)(t0 + G) * TILE,
                    TILE_BYTES, mb0 + 8);
        }
    }

    float v0 = 0.f, v1 = 0.f, v2 = 0.f, v3 = 0.f;  // cls, objc, noobj, coord
    int ph0 = 0, ph1 = 0;                          // per-stage phase parity

    int buf = 0;
    for (int t = t0; t < ntiles; t += G, buf ^= 1) {
        // ---- wait for this stage's TMA completion
        if (buf == 0) { mbar_wait(mb0, ph0);     ph0 ^= 1; }
        else          { mbar_wait(mb0 + 8, ph1); ph1 ^= 1; }

        const float* sp = dyn_smem + buf * BUF_FLOATS;
        const float* st = sp + TILE;

        if (grpA) {
            // ---- B1: per-cell noobj + obj-box compaction (threads 0..97)
            if (tid < ITEMS * CELLS) {
                const int base = tid * CH;
                if (st[base + 4] == 0.0f) {
                    const float d4 = sp[base + 4] - st[base + 4];
                    const float d9 = sp[base + 9] - st[base + 9];
                    v2 += d4 * d4 + d9 * d9;
                } else {
                    const int s_ = (tid >= CELLS);
                    const int slot = atomicAdd(&cnt[s_], 1);
                    #pragma unroll
                    for (int k = 0; k < 2; k++) {
                        const int j   = slot * 2 + k;
                        const int off = base + k * 5;
                        boxoff[s_][j] = (short)off;
                        const float pcx = sp[off],     pcy = sp[off + 1];
                        const float pw  = sp[off + 2], ph  = sp[off + 3];
                        bpx[s_][j][0] = pcx - pw * 0.5f;  bpx[s_][j][1] = pcy - ph * 0.5f;
                        bpx[s_][j][2] = pcx + pw * 0.5f;  bpx[s_][j][3] = pcy + ph * 0.5f;
                        const float tcx = st[off],     tcy = st[off + 1];
                        const float tw  = st[off + 2], th  = st[off + 3];
                        btx[s_][j][0] = tcx - tw * 0.5f;  btx[s_][j][1] = tcy - th * 0.5f;
                        btx[s_][j][2] = tcx + tw * 0.5f;  btx[s_][j][3] = tcy + th * 0.5f;
                    }
                }
            }
            asm volatile("bar.sync 1, 128;" ::: "memory");   // boxes + cnt ready (grpA)

            // ---- C: cmask[j] = any obj pred box overlaps target box j.
            // iou > 0 <=> inter > 0 (union > 0 since w,h >= 0.05).
            const int sub = tid >> 6;                  // 64 threads per item
            const int nb  = cnt[sub] * 2;
            for (int j = (tid & 63); j < nb; j += 64) {
                const float tx0 = btx[sub][j][0], ty0 = btx[sub][j][1];
                const float tx1 = btx[sub][j][2], ty1 = btx[sub][j][3];
                bool hit = false;
                for (int i = 0; i < nb; i++) {
                    const float w = fminf(bpx[sub][i][2], tx1) - fmaxf(bpx[sub][i][0], tx0);
                    const float h = fminf(bpx[sub][i][3], ty1) - fmaxf(bpx[sub][i][1], ty0);
                    if (w > 0.0f && h > 0.0f) { hit = true; break; }
                }
                if (hit) {
                    const int off = boxoff[sub][j];
                    const float dx = sp[off]     - st[off];
                    const float dy = sp[off + 1] - st[off + 1];
                    const float dw = sqrtf(sp[off + 2]) - sqrtf(st[off + 2]);
                    const float dh = sqrtf(sp[off + 3]) - sqrtf(st[off + 3]);
                    v3 += dx * dx + dy * dy + dw * dw + dh * dh;
                    const float dc = sp[off + 4] - st[off + 4];
                    v1 += dc * dc;
                }
            }
        } else {
            // ---- B2: class loss, one thread per cell, unrolled over 20 classes
            if (ctid < ITEMS * CELLS) {
                const int base = ctid * CH;
                const float m = st[base + 4];          // 0 or 1
                float s = 0.0f;
                #pragma unroll
                for (int c = 10; c < 30; c++) {
                    const float d = sp[base + c] - st[base + c];
                    s += d * d;
                }
                v0 += m * s;
            }
        }
        __syncthreads();                               // all reads done; buffer reusable
        if (tid < ITEMS) cnt[tid] = 0;

        // ---- refill this stage with tile t + 2G (thread 0 only)
        const int nt2 = t + 2 * G;
        if (tid == 0 && nt2 < ntiles) {
            const uint32_t sb = sbase + buf * (uint32_t)BUF_BYTES;
            const uint32_t mb = mb0 + buf * 8;
            mbar_expect_tx(mb, BUF_BYTES);
            bulk_ld(sb, pred + (size_t)nt2 * TILE, TILE_BYTES, mb);
            bulk_ld(sb + TILE_BYTES, targ + (size_t)nt2 * TILE, TILE_BYTES, mb);
        }
    }

    // ---- block reduction of per-thread accumulators
    #pragma unroll
    for (int o = 16; o > 0; o >>= 1) {
        v0 += __shfl_down_sync(0xffffffffu, v0, o);
        v1 += __shfl_down_sync(0xffffffffu, v1, o);
        v2 += __shfl_down_sync(0xffffffffu, v2, o);
        v3 += __shfl_down_sync(0xffffffffu, v3, o);
    }
    const int lane = tid & 31, warp = tid >> 5;
    if (lane == 0) {
        red[warp][0] = v0; red[warp][1] = v1;
        red[warp][2] = v2; red[warp][3] = v3;
    }
    __syncthreads();
    if (tid < 4) {
        float s = 0.0f;
        #pragma unroll
        for (int w = 0; w < NT / 32; w++) s += red[w][tid];
        atomicAdd(&g_acc[tid], (double)s);
        __threadfence();
    }
    __syncthreads();

    // ---- ticket; last CTA finalizes + resets for next graph replay
    if (tid == 0) {
        const unsigned int old = atomicAdd(&g_ticket, 1u);
        if (old == gridDim.x - 1) is_last = 1;
    }
    __syncthreads();
    if (is_last && tid == 0) {
        const double cls_s   = atomicAdd(&g_acc[0], 0.0);
        const double objc_s  = atomicAdd(&g_acc[1], 0.0);
        const double noobj_s = atomicAdd(&g_acc[2], 0.0);
        const double coord_s = atomicAdd(&g_acc[3], 0.0);
        const double invB = 1.0 / (double)(ntiles * ITEMS);
        const float bcls   = (float)(cls_s * invB);
        const float bobj   = (float)((objc_s + 0.5 * noobj_s) * invB);
        const float bcoord = (float)(coord_s * 5.0 * invB);
        out[0] = bcls + bobj + bcoord;
        out[1] = bcls;
        out[2] = bobj;
        out[3] = bcoord;
        g_acc[0] = 0.0; g_acc[1] = 0.0; g_acc[2] = 0.0; g_acc[3] = 0.0;
        __threadfence();
        g_ticket = 0u;
    }
}

extern "C" void kernel_launch(void* const* d_in, const int* in_sizes, int n_in,
                              void* d_out, int out_size) {
    const float* pred = (const float*)d_in[0];
    const float* targ = (const float*)d_in[1];
    float* out = (float*)d_out;
    const int B = in_sizes[0] / PERB;        // 8192
    const int ntiles = B / ITEMS;            // 4096

    static bool attr_set = false;            // idempotent host-side config
    if (!attr_set) {
        cudaFuncSetAttribute(yolo_loss_tma,
                             cudaFuncAttributeMaxDynamicSharedMemorySize,
                             STAGES * BUF_BYTES);
        attr_set = true;
    }
    const int grid = (ntiles < GRID_CTAS) ? ntiles : GRID_CTAS;
    yolo_loss_tma<<<grid, NT, STAGES * BUF_BYTES>>>(pred, targ, out, ntiles);
}